// round 1
// baseline (speedup 1.0000x reference)
#include <cuda_runtime.h>
#include <math.h>

#define LF 104          // node feature length
#define SS 500          // sink outputs / classes
#define MM 64           // molecules
#define TT 32           // topological levels
#define WW 256          // nodes per level
#define NROWS (MM*WW)   // 16384
#define RT 64           // rows per CTA
#define TXN 26          // col-thread groups (26*4 = 104 cols)
#define TYN 8
#define NTHR (TXN*TYN)  // 208 threads
#define ITS 68          // padded smem input row stride (conflict-free, 16B-aligned)
#define KC 52           // K chunk

__device__ float g_hA[NROWS*LF];
__device__ float g_hB[NROWS*LF];
__device__ float g_sink[MM*SS];

typedef unsigned long long u64;

__device__ __forceinline__ u64 bcast2(float x){
    u64 r; asm("mov.b64 %0, {%1, %1};" : "=l"(r) : "f"(x)); return r;
}
__device__ __forceinline__ void fma2(u64 &d, u64 a, u64 b){
    asm("fma.rn.f32x2 %0, %1, %2, %0;" : "+l"(d) : "l"(a), "l"(b));
}
__device__ __forceinline__ float2 unpack2(u64 a){
    float2 v; asm("mov.b64 {%0, %1}, %2;" : "=f"(v.x), "=f"(v.y) : "l"(a)); return v;
}

// Unified level kernel.
//  t == 0: nchunk = 2, Wm = W_single [104,104], input = context[:,0]
//  t >= 1: nchunk = 6, Wm = W_int2  [312,104], input = [ctx | par0 | par1]
// Output buffer: (t&1) ? g_hB : g_hA ; source: the other one.
__global__ void __launch_bounds__(NTHR) level_kernel(
    const float* __restrict__ ctx, const int* __restrict__ pidx,
    const float* __restrict__ Wm, const float* __restrict__ bias,
    int t, int nchunk)
{
    __shared__ float sW[KC*LF];     // 52x104 weight chunk
    __shared__ float sIn[KC*ITS];   // 52x64 transposed inputs (padded)

    const float* hsrc = (t & 1) ? g_hA : g_hB;
    float*       hdst = (t & 1) ? g_hB : g_hA;

    const int tid = threadIdx.x;
    const int tx = tid % TXN;       // output col group (4 cols)
    const int ty = tid / TXN;       // row group (8 rows)
    const int rbase = blockIdx.x * RT;

    u64 acc[4][4];                  // [rowpair][col], f32x2 lanes = (even row, odd row)
    #pragma unroll
    for (int i = 0; i < 4; ++i)
        #pragma unroll
        for (int j = 0; j < 4; ++j) acc[i][j] = 0ULL;

    for (int c = 0; c < nchunk; ++c) {
        const int sg = c >> 1;          // 0: ctx, 1: parent0, 2: parent1
        const int koff = (c & 1) * KC;  // offset inside the 104-wide segment

        // ---- stage weight chunk: rows [c*52, c*52+52) of Wm ----
        #pragma unroll 1
        for (int idx = tid; idx < KC*26; idx += NTHR) {
            int k = idx / 26, q = idx % 26;
            *(float4*)&sW[k*LF + q*4] =
                *(const float4*)&Wm[(size_t)(c*KC + k)*LF + q*4];
        }
        // ---- stage inputs transposed: sIn[k][r] ----
        #pragma unroll 1
        for (int idx = tid; idx < RT*13; idx += NTHR) {
            int r = idx & (RT-1);
            int ql = idx >> 6;               // 13 float4 per row per chunk
            int grow = rbase + r;
            int m = grow >> 8, w = grow & 255;
            const float* src;
            if (sg == 0) {
                src = ctx + (((size_t)m*TT + t)*WW + w)*LF + koff + ql*4;
            } else {
                int p = pidx[(((size_t)m*(TT-1) + (t-1))*WW + w)*2 + (sg-1)];
                src = hsrc + ((size_t)m*WW + p)*LF + koff + ql*4;
            }
            float4 v = *(const float4*)src;
            int k = ql*4;
            sIn[(k  )*ITS + r] = v.x;
            sIn[(k+1)*ITS + r] = v.y;
            sIn[(k+2)*ITS + r] = v.z;
            sIn[(k+3)*ITS + r] = v.w;
        }
        __syncthreads();

        // ---- compute: 8 rows x 4 cols per thread, packed f32x2 over row pairs ----
        const float* wrow = &sW[tx*4];
        const float* irow = &sIn[ty*8];
        #pragma unroll 4
        for (int k = 0; k < KC; ++k) {
            float4 wf = *(const float4*)(wrow + (size_t)k*LF);
            u64 wb0 = bcast2(wf.x), wb1 = bcast2(wf.y);
            u64 wb2 = bcast2(wf.z), wb3 = bcast2(wf.w);
            const u64* ap = (const u64*)(irow + (size_t)k*ITS);
            u64 a0 = ap[0], a1 = ap[1], a2 = ap[2], a3 = ap[3];
            fma2(acc[0][0], a0, wb0); fma2(acc[0][1], a0, wb1);
            fma2(acc[0][2], a0, wb2); fma2(acc[0][3], a0, wb3);
            fma2(acc[1][0], a1, wb0); fma2(acc[1][1], a1, wb1);
            fma2(acc[1][2], a1, wb2); fma2(acc[1][3], a1, wb3);
            fma2(acc[2][0], a2, wb0); fma2(acc[2][1], a2, wb1);
            fma2(acc[2][2], a2, wb2); fma2(acc[2][3], a2, wb3);
            fma2(acc[3][0], a3, wb0); fma2(acc[3][1], a3, wb1);
            fma2(acc[3][2], a3, wb2); fma2(acc[3][3], a3, wb3);
        }
        __syncthreads();
    }

    // ---- epilogue: + bias, ReLU, store ----
    float4 bv = *(const float4*)&bias[tx*4];
    #pragma unroll
    for (int rp = 0; rp < 4; ++rp) {
        float2 v0 = unpack2(acc[rp][0]);
        float2 v1 = unpack2(acc[rp][1]);
        float2 v2 = unpack2(acc[rp][2]);
        float2 v3 = unpack2(acc[rp][3]);
        float4 oe = make_float4(fmaxf(v0.x + bv.x, 0.f), fmaxf(v1.x + bv.y, 0.f),
                                fmaxf(v2.x + bv.z, 0.f), fmaxf(v3.x + bv.w, 0.f));
        float4 oo = make_float4(fmaxf(v0.y + bv.x, 0.f), fmaxf(v1.y + bv.y, 0.f),
                                fmaxf(v2.y + bv.z, 0.f), fmaxf(v3.y + bv.w, 0.f));
        size_t r0 = (size_t)rbase + ty*8 + rp*2;
        *(float4*)&hdst[r0*LF + tx*4]     = oe;
        *(float4*)&hdst[(r0+1)*LF + tx*4] = oo;
    }
}

// Sink: sink_out[m,s] = dot(concat_{j<7} h_last[m, sidx[m,j], :], W_sink7[:, s])
// grid (64, 4), block 128. Deterministic (no atomics).
__global__ void __launch_bounds__(128) sink_kernel(
    const int* __restrict__ sidx, const float* __restrict__ Wk)
{
    __shared__ float sh[7*LF];
    const int m = blockIdx.x;
    const int tid = threadIdx.x;
    const float* h = g_hB;   // level 31 output lives in g_hB (31 is odd)

    for (int idx = tid; idx < 7*LF; idx += 128) {
        int j = idx / LF, l = idx % LF;
        int p = sidx[m*7 + j];
        sh[idx] = h[((size_t)m*WW + p)*LF + l];
    }
    __syncthreads();

    int s = blockIdx.y * 128 + tid;
    if (s < SS) {
        float acc = 0.f;
        #pragma unroll 8
        for (int kk = 0; kk < 7*LF; ++kk)
            acc = fmaf(sh[kk], Wk[(size_t)kk*SS + s], acc);
        g_sink[(size_t)m*SS + s] = acc;
    }
}

// Final head: avg over molecules + b_sink7, 500x500 matvec + b_cls, sigmoid.
__global__ void __launch_bounds__(512) final_kernel(
    const float* __restrict__ bs, const float* __restrict__ Wc,
    const float* __restrict__ bc, float* __restrict__ out)
{
    __shared__ float avg[SS];
    const int tid = threadIdx.x;
    for (int s = tid; s < SS; s += 512) {
        float a = 0.f;
        #pragma unroll 8
        for (int m = 0; m < MM; ++m) a += g_sink[(size_t)m*SS + s];
        avg[s] = a * (1.0f/MM) + bs[s];
    }
    __syncthreads();
    for (int s = tid; s < SS; s += 512) {
        float acc = bc[s];
        #pragma unroll 4
        for (int i = 0; i < SS; ++i)
            acc = fmaf(avg[i], Wc[(size_t)i*SS + s], acc);
        out[s] = 1.0f / (1.0f + expf(-acc));
    }
}

extern "C" void kernel_launch(void* const* d_in, const int* in_sizes, int n_in,
                              void* d_out, int out_size)
{
    const float* ctx      = (const float*)d_in[0];
    const int*   pidx     = (const int*)  d_in[1];
    const int*   sidx     = (const int*)  d_in[2];
    const float* W_single = (const float*)d_in[3];
    const float* b_single = (const float*)d_in[4];
    const float* W_int2   = (const float*)d_in[5];
    const float* b_int2   = (const float*)d_in[6];
    const float* W_sink7  = (const float*)d_in[7];
    const float* b_sink7  = (const float*)d_in[8];
    const float* W_cls    = (const float*)d_in[9];
    const float* b_cls    = (const float*)d_in[10];
    float* out = (float*)d_out;

    dim3 grid(NROWS / RT);   // 256 CTAs

    // level 0: single-node linear
    level_kernel<<<grid, NTHR>>>(ctx, pidx, W_single, b_single, 0, 2);
    // levels 1..31: internal nodes with 2 parents
    for (int t = 1; t < TT; ++t)
        level_kernel<<<grid, NTHR>>>(ctx, pidx, W_int2, b_int2, t, 6);
    // sink + head
    sink_kernel<<<dim3(MM, (SS + 127) / 128), 128>>>(sidx, W_sink7);
    final_kernel<<<1, 512>>>(b_sink7, W_cls, b_cls, out);
}